// round 4
// baseline (speedup 1.0000x reference)
#include <cuda_runtime.h>

// Problem constants
#define F_DENSE  13
#define F_SPARSE 26
#define NF       39          // F_DENSE + F_SPARSE
#define E_DIM    16
#define VOC      100000
#define H1       512
#define H2       256
#define D_IN     624         // (13+26)*16

#define SMP_PER_BLOCK 16     // 2 samples per warp, 8 warps, 256 threads
#define THREADS       256

// Scratch (device globals; no allocation allowed)
__device__ float g_w2eff[H1];
__device__ float g_w1eff[D_IN];
__device__ float g_CONST;

// ---------------------------------------------------------------------------
// Prep 1: w2eff[k] = sum_j Lw2[k,j] * g2[j]
// ---------------------------------------------------------------------------
__global__ void prep_w2eff(const float* __restrict__ Lw2,
                           const float* __restrict__ g2) {
    int w    = (blockIdx.x * blockDim.x + threadIdx.x) >> 5;
    int lane = threadIdx.x & 31;
    if (w >= H1) return;
    float acc = 0.f;
#pragma unroll
    for (int i = 0; i < H2 / 32; i++) {
        int j = lane + i * 32;
        acc = fmaf(__ldg(Lw2 + w * H2 + j), __ldg(g2 + j), acc);
    }
#pragma unroll
    for (int o = 16; o; o >>= 1) acc += __shfl_xor_sync(0xffffffffu, acc, o);
    if (lane == 0) g_w2eff[w] = acc;
}

// ---------------------------------------------------------------------------
// Prep 2: scalar constant
// ---------------------------------------------------------------------------
__global__ void prep_const(const float* __restrict__ Lb1,
                           const float* __restrict__ g1,
                           const float* __restrict__ be1,
                           const float* __restrict__ Lb2,
                           const float* __restrict__ g2,
                           const float* __restrict__ be2) {
    const float inv = rsqrtf(1.f + 1e-5f);
    int k = threadIdx.x;
    float w2e = g_w2eff[k];
    float v = inv * inv * g1[k] * w2e * Lb1[k] + inv * be1[k] * w2e;
    if (k < H2) v += inv * g2[k] * Lb2[k] + be2[k];
    __shared__ float sh[H1];
    sh[k] = v;
    __syncthreads();
    for (int s = H1 / 2; s; s >>= 1) {
        if (k < s) sh[k] += sh[k + s];
        __syncthreads();
    }
    if (k == 0) g_CONST = sh[0];
}

// ---------------------------------------------------------------------------
// Prep 3: w1eff[d] = sum_k Lw1[d,k] * g1[k] * w2eff[k]
// ---------------------------------------------------------------------------
__global__ void prep_w1eff(const float* __restrict__ Lw1,
                           const float* __restrict__ g1) {
    int w    = (blockIdx.x * blockDim.x + threadIdx.x) >> 5;
    int lane = threadIdx.x & 31;
    if (w >= D_IN) return;
    float acc = 0.f;
#pragma unroll
    for (int i = 0; i < H1 / 32; i++) {
        int k = lane + i * 32;
        acc = fmaf(__ldg(Lw1 + w * H1 + k), __ldg(g1 + k) * g_w2eff[k], acc);
    }
#pragma unroll
    for (int o = 16; o; o >>= 1) acc += __shfl_xor_sync(0xffffffffu, acc, o);
    if (lane == 0) g_w1eff[w] = acc;
}

// ---------------------------------------------------------------------------
// emb2 pass chunk: feeds se / ss / hd.  CH loads issued back-to-back.
// ---------------------------------------------------------------------------
template <int CH>
__device__ __forceinline__ void emb2_chunk(
    int c0, const int* xi, const float* xv, int e,
    const float* __restrict__ emb2, const float* sh_w1e,
    float& se, float& ss, float& hd)
{
    float a[CH];
    int   off[CH];
#pragma unroll
    for (int j = 0; j < CH; j++) {
        int s  = c0 + j;
        off[j] = (s * VOC + xi[F_DENSE + s]) * E_DIM + e;
    }
#pragma unroll
    for (int j = 0; j < CH; j++) a[j] = __ldg(emb2 + off[j]);
#pragma unroll
    for (int j = 0; j < CH; j++) {
        int s = c0 + j;
        float sev = a[j] * xv[F_DENSE + s];
        se += sev;
        ss  = fmaf(sev, sev, ss);
        hd  = fmaf(sev, sh_w1e[(F_DENSE + s) * E_DIM + e], hd);
    }
}

// ---------------------------------------------------------------------------
// emb1 pass chunk: feeds fm1 only.
// ---------------------------------------------------------------------------
template <int CH>
__device__ __forceinline__ void emb1_chunk(
    int c0, const int* xi, const float* xv, int e,
    const float* __restrict__ emb1,
    float& fm1)
{
    float a[CH];
    int   off[CH];
#pragma unroll
    for (int j = 0; j < CH; j++) {
        int s  = c0 + j;
        off[j] = (s * VOC + xi[F_DENSE + s]) * E_DIM + e;
    }
#pragma unroll
    for (int j = 0; j < CH; j++) a[j] = __ldg(emb1 + off[j]);
#pragma unroll
    for (int j = 0; j < CH; j++)
        fm1 = fmaf(a[j], xv[F_DENSE + c0 + j], fm1);
}

// ---------------------------------------------------------------------------
// Main kernel: 16 lanes per sample (lane = e), 2 samples per warp.
// ---------------------------------------------------------------------------
__global__ __launch_bounds__(THREADS, 6) void deepfm_main(
    const int*   __restrict__ Xi,
    const float* __restrict__ Xv,
    const float* __restrict__ W1,
    const float* __restrict__ b1,
    const float* __restrict__ emb1,
    const float* __restrict__ W2,
    const float* __restrict__ b2,
    const float* __restrict__ emb2,
    const float* __restrict__ bias,
    float*       __restrict__ out,
    int n) {
    const float inv2 = 1.f / (1.f + 1e-5f);   // inv^2 = 1/(1+eps)

    __shared__ int   sh_xi[SMP_PER_BLOCK * NF];
    __shared__ float sh_xv[SMP_PER_BLOCK * NF];
    __shared__ float sh_w1e[D_IN];

    int tid  = threadIdx.x;
    int base = blockIdx.x * SMP_PER_BLOCK;

    // Coalesced staging
    {
        int tile = SMP_PER_BLOCK * NF;
        int gmax = n * NF - base * NF;
        for (int i = tid; i < tile; i += THREADS) {
            if (i < gmax) {
                sh_xi[i] = Xi[base * NF + i];
                sh_xv[i] = Xv[base * NF + i];
            }
        }
        for (int i = tid; i < D_IN; i += THREADS) sh_w1e[i] = g_w1eff[i];
    }
    __syncthreads();

    int lane = tid & 31;
    int e    = lane & 15;          // embedding column handled by this lane
    int sub  = lane >> 4;          // sample within warp (0/1)
    int warp = tid >> 5;
    int smp  = warp * 2 + sub;
    int b    = base + smp;
    if (b >= n) return;

    const int*   xi = sh_xi + smp * NF;
    const float* xv = sh_xv + smp * NF;

    float fm1 = 0.f;   // first-order sum (partial over this lane's e)
    float se  = 0.f;   // sum_emb[e]
    float ss  = 0.f;   // sumsq[e]
    float hd  = 0.f;   // h . w1eff (partial)

    // Pass A: emb2 gathers (13 loads in flight per chunk)
    emb2_chunk<13>( 0, xi, xv, e, emb2, sh_w1e, se, ss, hd);
    emb2_chunk<13>(13, xi, xv, e, emb2, sh_w1e, se, ss, hd);

    // Pass B: emb1 gathers
    emb1_chunk<13>( 0, xi, xv, e, emb1, fm1);
    emb1_chunk<13>(13, xi, xv, e, emb1, fm1);

    // Dense features (params L2-resident)
#pragma unroll
    for (int f = 0; f < F_DENSE; f++) {
        float x  = (float)xi[f];
        float v  = xv[f];
        int   o  = f * E_DIM + e;
        float sl = fmaf(x, __ldg(W2 + o), __ldg(b2 + o));       // sec_lin
        fm1 = fmaf(fmaf(x, __ldg(W1 + o), __ldg(b1 + o)), v, fm1);
        se += sl;
        ss  = fmaf(sl, sl, ss);
        hd  = fmaf(sl, sh_w1e[o], hd);
    }

    // Per-lane combined partial (per-e exact)
    float r = fm1 + 0.5f * (se * se - ss) + inv2 * hd;

    // Fold 16 lanes (xor<16 stays within each half-warp / sample)
#pragma unroll
    for (int o = 1; o < 16; o <<= 1) r += __shfl_xor_sync(0xffffffffu, r, o);

    if (e == 0) out[b] = r + g_CONST + __ldg(bias + b);
}

// ---------------------------------------------------------------------------
extern "C" void kernel_launch(void* const* d_in, const int* in_sizes, int n_in,
                              void* d_out, int out_size) {
    const int*   Xi   = (const int*)  d_in[0];
    const float* Xv   = (const float*)d_in[1];
    const float* W1   = (const float*)d_in[2];
    const float* b1   = (const float*)d_in[3];
    const float* emb1 = (const float*)d_in[4];
    const float* W2   = (const float*)d_in[5];
    const float* b2   = (const float*)d_in[6];
    const float* emb2 = (const float*)d_in[7];
    const float* Lw1  = (const float*)d_in[8];
    const float* Lb1  = (const float*)d_in[9];
    const float* g1   = (const float*)d_in[10];
    const float* be1  = (const float*)d_in[11];
    const float* Lw2  = (const float*)d_in[12];
    const float* Lb2  = (const float*)d_in[13];
    const float* g2   = (const float*)d_in[14];
    const float* be2  = (const float*)d_in[15];
    const float* bias = (const float*)d_in[16];
    float* out = (float*)d_out;

    prep_w2eff<<<(H1 * 32 + 255) / 256, 256>>>(Lw2, g2);
    prep_const<<<1, H1>>>(Lb1, g1, be1, Lb2, g2, be2);
    prep_w1eff<<<(D_IN * 32 + 255) / 256, 256>>>(Lw1, g1);

    int n = out_size;
    int blocks = (n + SMP_PER_BLOCK - 1) / SMP_PER_BLOCK;
    deepfm_main<<<blocks, THREADS>>>(Xi, Xv, W1, b1, emb1, W2, b2, emb2,
                                     bias, out, n);
}

// round 5
// speedup vs baseline: 1.8509x; 1.8509x over previous
#include <cuda_runtime.h>

// Problem constants
#define F_DENSE  13
#define F_SPARSE 26
#define NF       39          // F_DENSE + F_SPARSE
#define E_DIM    16
#define VOC      100000
#define H1       512
#define H2       256
#define D_IN     624         // (13+26)*16

#define THREADS       256
#define SMP_PER_WARP  4      // 8 lanes (float2 over e) per sample
#define SMP_PER_BLOCK 32     // 8 warps * 4

// Scratch (device globals; no allocation allowed)
__device__ float g_w2eff[H1];
__device__ __align__(16) float g_w1eff[D_IN];
__device__ float g_CONST;

// ---------------------------------------------------------------------------
// Prep 1: w2eff[k] = sum_j Lw2[k,j] * g2[j]
// ---------------------------------------------------------------------------
__global__ void prep_w2eff(const float* __restrict__ Lw2,
                           const float* __restrict__ g2) {
    int w    = (blockIdx.x * blockDim.x + threadIdx.x) >> 5;
    int lane = threadIdx.x & 31;
    if (w >= H1) return;
    float acc = 0.f;
#pragma unroll
    for (int i = 0; i < H2 / 32; i++) {
        int j = lane + i * 32;
        acc = fmaf(__ldg(Lw2 + w * H2 + j), __ldg(g2 + j), acc);
    }
#pragma unroll
    for (int o = 16; o; o >>= 1) acc += __shfl_xor_sync(0xffffffffu, acc, o);
    if (lane == 0) g_w2eff[w] = acc;
}

// ---------------------------------------------------------------------------
// Prep 2: scalar constant
// ---------------------------------------------------------------------------
__global__ void prep_const(const float* __restrict__ Lb1,
                           const float* __restrict__ g1,
                           const float* __restrict__ be1,
                           const float* __restrict__ Lb2,
                           const float* __restrict__ g2,
                           const float* __restrict__ be2) {
    const float inv = rsqrtf(1.f + 1e-5f);
    int k = threadIdx.x;
    float w2e = g_w2eff[k];
    float v = inv * inv * g1[k] * w2e * Lb1[k] + inv * be1[k] * w2e;
    if (k < H2) v += inv * g2[k] * Lb2[k] + be2[k];
    __shared__ float sh[H1];
    sh[k] = v;
    __syncthreads();
    for (int s = H1 / 2; s; s >>= 1) {
        if (k < s) sh[k] += sh[k + s];
        __syncthreads();
    }
    if (k == 0) g_CONST = sh[0];
}

// ---------------------------------------------------------------------------
// Prep 3: w1eff[d] = sum_k Lw1[d,k] * g1[k] * w2eff[k]
// ---------------------------------------------------------------------------
__global__ void prep_w1eff(const float* __restrict__ Lw1,
                           const float* __restrict__ g1) {
    int w    = (blockIdx.x * blockDim.x + threadIdx.x) >> 5;
    int lane = threadIdx.x & 31;
    if (w >= D_IN) return;
    float acc = 0.f;
#pragma unroll
    for (int i = 0; i < H1 / 32; i++) {
        int k = lane + i * 32;
        acc = fmaf(__ldg(Lw1 + w * H1 + k), __ldg(g1 + k) * g_w2eff[k], acc);
    }
#pragma unroll
    for (int o = 16; o; o >>= 1) acc += __shfl_xor_sync(0xffffffffu, acc, o);
    if (lane == 0) g_w1eff[w] = acc;
}

// ---------------------------------------------------------------------------
// Process CH sparse slots starting at c0: gather emb2 batch (feeds se/ss/hd),
// then reuse the same offsets for the emb1 batch (feeds fm1).
// All state scalar-or-float2 so CH=13 fits comfortably in registers.
// ---------------------------------------------------------------------------
template <int CH>
__device__ __forceinline__ void slots_chunk(
    int c0, const int* __restrict__ xi, const float* __restrict__ xv, int h,
    const float2* __restrict__ e1t, const float2* __restrict__ e2t,
    const float2* __restrict__ w1e2,
    float& fm1, float2& se, float& ss, float& hd)
{
    int   off[CH];
    float vv[CH];
#pragma unroll
    for (int j = 0; j < CH; j++) {
        int s  = c0 + j;
        int id = __ldg(xi + F_DENSE + s);
        vv[j]  = __ldg(xv + F_DENSE + s);
        off[j] = (s * VOC + id) * (E_DIM / 2) + h;    // float2 index
    }
    {
        float2 A[CH];
#pragma unroll
        for (int j = 0; j < CH; j++) A[j] = __ldg(e2t + off[j]);
#pragma unroll
        for (int j = 0; j < CH; j++) {
            float v = vv[j];
            float2 sev = make_float2(A[j].x * v, A[j].y * v);
            se.x += sev.x; se.y += sev.y;
            ss = fmaf(sev.x, sev.x, fmaf(sev.y, sev.y, ss));
            float2 w = __ldg(w1e2 + (F_DENSE + c0 + j) * (E_DIM / 2) + h);
            hd = fmaf(sev.x, w.x, fmaf(sev.y, w.y, hd));
        }
    }
    {
        float2 A[CH];
#pragma unroll
        for (int j = 0; j < CH; j++) A[j] = __ldg(e1t + off[j]);
#pragma unroll
        for (int j = 0; j < CH; j++)
            fm1 = fmaf(A[j].x + A[j].y, vv[j], fm1);
    }
}

// ---------------------------------------------------------------------------
// Main kernel: 8 lanes per sample (lane-h = e-pair via float2),
// 4 samples per warp, 256 threads => 32 samples per block, 512 blocks.
// No smem, no launch_bounds cap: ptxas keeps the load batches intact.
// ---------------------------------------------------------------------------
__global__ void deepfm_main(
    const int*   __restrict__ Xi,
    const float* __restrict__ Xv,
    const float* __restrict__ W1,
    const float* __restrict__ b1,
    const float* __restrict__ emb1,
    const float* __restrict__ W2,
    const float* __restrict__ b2,
    const float* __restrict__ emb2,
    const float* __restrict__ bias,
    float*       __restrict__ out,
    int n) {
    const float inv2 = 1.f / (1.f + 1e-5f);   // inv^2 = 1/(1+eps)

    int tid  = threadIdx.x;
    int lane = tid & 31;
    int h    = lane & 7;           // float2 slot within 64B row (e = 2h, 2h+1)
    int sub  = lane >> 3;          // sample within warp (0..3)
    int warp = tid >> 5;
    int b    = blockIdx.x * SMP_PER_BLOCK + warp * SMP_PER_WARP + sub;
    if (b >= n) return;

    const int*   xi = Xi + b * NF;
    const float* xv = Xv + b * NF;

    const float2* e1t  = (const float2*)emb1;
    const float2* e2t  = (const float2*)emb2;
    const float2* w1e2 = (const float2*)g_w1eff;
    const float2* W1_2 = (const float2*)W1;
    const float2* b1_2 = (const float2*)b1;
    const float2* W2_2 = (const float2*)W2;
    const float2* b2_2 = (const float2*)b2;

    float  fm1 = 0.f;
    float2 se  = make_float2(0.f, 0.f);
    float  ss  = 0.f;
    float  hd  = 0.f;

    // Sparse gathers (DRAM-bound), two chunks of 13 slots
    slots_chunk<13>( 0, xi, xv, h, e1t, e2t, w1e2, fm1, se, ss, hd);
    slots_chunk<13>(13, xi, xv, h, e1t, e2t, w1e2, fm1, se, ss, hd);

    // Dense features (all L1/L2-resident broadcast loads)
#pragma unroll
    for (int f = 0; f < F_DENSE; f++) {
        float x = (float)__ldg(xi + f);
        float v = __ldg(xv + f);
        int   o = f * (E_DIM / 2) + h;
        float2 w2 = __ldg(W2_2 + o);
        float2 c2 = __ldg(b2_2 + o);
        float2 sl = make_float2(fmaf(x, w2.x, c2.x), fmaf(x, w2.y, c2.y));
        float2 w1 = __ldg(W1_2 + o);
        float2 c1 = __ldg(b1_2 + o);
        fm1 = fmaf(fmaf(x, w1.x, c1.x) + fmaf(x, w1.y, c1.y), v, fm1);
        se.x += sl.x; se.y += sl.y;
        ss = fmaf(sl.x, sl.x, fmaf(sl.y, sl.y, ss));
        float2 we = __ldg(w1e2 + o);
        hd = fmaf(sl.x, we.x, fmaf(sl.y, we.y, hd));
    }

    // Per-lane partial; fm_second per-e exact (each e owned by one lane)
    float r = fm1 + 0.5f * (se.x * se.x + se.y * se.y - ss) + inv2 * hd;

    // Fold the 8 lanes of this sample (xor<8 stays within the octet)
    r += __shfl_xor_sync(0xffffffffu, r, 1);
    r += __shfl_xor_sync(0xffffffffu, r, 2);
    r += __shfl_xor_sync(0xffffffffu, r, 4);

    if (h == 0) out[b] = r + g_CONST + __ldg(bias + b);
}

// ---------------------------------------------------------------------------
extern "C" void kernel_launch(void* const* d_in, const int* in_sizes, int n_in,
                              void* d_out, int out_size) {
    const int*   Xi   = (const int*)  d_in[0];
    const float* Xv   = (const float*)d_in[1];
    const float* W1   = (const float*)d_in[2];
    const float* b1   = (const float*)d_in[3];
    const float* emb1 = (const float*)d_in[4];
    const float* W2   = (const float*)d_in[5];
    const float* b2   = (const float*)d_in[6];
    const float* emb2 = (const float*)d_in[7];
    const float* Lw1  = (const float*)d_in[8];
    const float* Lb1  = (const float*)d_in[9];
    const float* g1   = (const float*)d_in[10];
    const float* be1  = (const float*)d_in[11];
    const float* Lw2  = (const float*)d_in[12];
    const float* Lb2  = (const float*)d_in[13];
    const float* g2   = (const float*)d_in[14];
    const float* be2  = (const float*)d_in[15];
    const float* bias = (const float*)d_in[16];
    float* out = (float*)d_out;

    prep_w2eff<<<(H1 * 32 + 255) / 256, 256>>>(Lw2, g2);
    prep_const<<<1, H1>>>(Lb1, g1, be1, Lb2, g2, be2);
    prep_w1eff<<<(D_IN * 32 + 255) / 256, 256>>>(Lw1, g1);

    int n = out_size;
    int blocks = (n + SMP_PER_BLOCK - 1) / SMP_PER_BLOCK;
    deepfm_main<<<blocks, THREADS>>>(Xi, Xv, W1, b1, emb1, W2, b2, emb2,
                                     bias, out, n);
}